// round 6
// baseline (speedup 1.0000x reference)
#include <cuda_runtime.h>
#include <cstdint>

// Encoding: B=64, C=512, N=784, K=32. x:(B,C,N) f32; out:(B,K,C) f32.
// K1: logits via mma.sync tf32 + softmax -> A^T (tf32, [b][k][n]) + wsum partials.
// K2: out = A x^T via direct-from-gmem fragments (no smem mainloop), fused epilogue.

#define CDIM 512
#define KD 32
#define NPIX 784
#define BDIM 64
#define CH1 9
#define TS 16
#define TILES1 49

__device__ float g_A[(size_t)BDIM * KD * NPIX];     // 6.4 MB, [b][k][n]
__device__ float g_wsum[BDIM * CH1 * KD];

__device__ __forceinline__ float rtf32(float v) {
    asm("cvt.rna.tf32.f32 %0, %1;" : "=f"(v) : "f"(v));
    return v;
}
__device__ __forceinline__ void mma8(float* d, uint32_t a0, uint32_t a1,
                                     uint32_t a2, uint32_t a3,
                                     uint32_t b0, uint32_t b1) {
    asm volatile(
        "mma.sync.aligned.m16n8k8.row.col.f32.tf32.tf32.f32 "
        "{%0,%1,%2,%3}, {%4,%5,%6,%7}, {%8,%9}, {%0,%1,%2,%3};"
        : "+f"(d[0]), "+f"(d[1]), "+f"(d[2]), "+f"(d[3])
        : "r"(a0), "r"(a1), "r"(a2), "r"(a3), "r"(b0), "r"(b1));
}
#define BITS(f) __float_as_uint(f)

// =========================== K1: logits + softmax ===========================
__global__ __launch_bounds__(256, 2) void enc_k1(const float* __restrict__ x,
                                                 const float* __restrict__ cw,
                                                 const float* __restrict__ scale) {
    const int b = blockIdx.x / CH1, ch = blockIdx.x % CH1;
    const int tile0 = ch * TILES1 / CH1, tile1 = (ch + 1) * TILES1 / CH1;
    const int t = threadIdx.x, w = t >> 5, l = t & 31;
    const int kt = w & 3, h = w >> 2;         // warp = (k-tile, c-half)

    __shared__ float x_s[TS * 516];
    __shared__ float xc_s[TS * 34];
    __shared__ float red_s[4 * 32 * 4];
    __shared__ float part_s[TS * 17];
    __shared__ float csq_s[KD], scl_s[KD];
    __shared__ float wsum_s[8][KD];

    if (t < KD) scl_s[t] = __ldg(&scale[t]);
    // csq from tf32-rounded cw: warp w -> k = 4w..4w+3
#pragma unroll
    for (int kk = 0; kk < 4; kk++) {
        int k = 4 * w + kk;
        float s = 0.f;
#pragma unroll
        for (int q = 0; q < 4; q++) {
            float4 v = __ldg((const float4*)&cw[k * CDIM + l * 16 + 4 * q]);
            float e0 = rtf32(v.x), e1 = rtf32(v.y), e2 = rtf32(v.z), e3 = rtf32(v.w);
            s += e0 * e0 + e1 * e1 + e2 * e2 + e3 * e3;
        }
#pragma unroll
        for (int o = 16; o; o >>= 1) s += __shfl_xor_sync(~0u, s, o);
        if (l == 0) csq_s[k] = s;
    }

    // persistent codeword B-fragments (tf32): warp covers k=8kt..+7, c-half h
    uint32_t cwf0[32], cwf1[32];
    const int crow = kt * 8 + (l >> 2), cp = l & 3;
#pragma unroll
    for (int s = 0; s < 32; s++) {
        int c = h * 256 + 8 * s + cp;
        cwf0[s] = BITS(rtf32(__ldg(&cw[crow * CDIM + c])));
        cwf1[s] = BITS(rtf32(__ldg(&cw[crow * CDIM + c + 4])));
    }

    float wsum_acc = 0.f;
    const float* xb = x + (size_t)b * CDIM * NPIX;
    const int nl = t & 15, cb16 = t >> 4;

    for (int tile = tile0; tile < tile1; tile++) {
        const int n0 = tile * TS;
        __syncthreads();
        // stage x tile (tf32-rounded) + fold xsq partial into staging
        float xsqp = 0.f;
#pragma unroll
        for (int i = 0; i < 32; i++) {
            int c = cb16 + 16 * i;
            float v = rtf32(__ldg(&xb[c * NPIX + n0 + nl]));
            x_s[nl * 516 + c] = v;
            xsqp = fmaf(v, v, xsqp);
        }
        part_s[nl * 17 + cb16] = xsqp;
        __syncthreads();

        // phase 1: xc = x . cw^T, 32 k-steps, 2 accumulation chains
        float dA[4] = {0.f, 0.f, 0.f, 0.f}, dB[4] = {0.f, 0.f, 0.f, 0.f};
        const int r0 = (l >> 2) * 516, r1 = ((l >> 2) + 8) * 516;
#pragma unroll
        for (int s = 0; s < 32; s++) {
            int c = h * 256 + 8 * s + cp;
            uint32_t a0 = BITS(x_s[r0 + c]);
            uint32_t a1 = BITS(x_s[r1 + c]);
            uint32_t a2 = BITS(x_s[r0 + c + 4]);
            uint32_t a3 = BITS(x_s[r1 + c + 4]);
            mma8((s & 1) ? dB : dA, a0, a1, a2, a3, cwf0[s], cwf1[s]);
        }
        float d4[4];
#pragma unroll
        for (int i = 0; i < 4; i++) d4[i] = dA[i] + dB[i];
        if (h == 1)
            *(float4*)&red_s[(kt * 32 + l) * 4] = make_float4(d4[0], d4[1], d4[2], d4[3]);
        __syncthreads();
        if (h == 0) {
            float4 rr = *(const float4*)&red_s[(kt * 32 + l) * 4];
            d4[0] += rr.x; d4[1] += rr.y; d4[2] += rr.z; d4[3] += rr.w;
            int rrow = l >> 2, cc = kt * 8 + 2 * (l & 3);
            *(float2*)&xc_s[rrow * 34 + cc] = make_float2(d4[0], d4[1]);
            *(float2*)&xc_s[(rrow + 8) * 34 + cc] = make_float2(d4[2], d4[3]);
        }
        __syncthreads();

        // softmax: warp w rows {w, w+8}, lane = k
#pragma unroll
        for (int r = 0; r < 2; r++) {
            int n = w + 8 * r;
            float xs = 0.f;
#pragma unroll
            for (int q = 0; q < 16; q++) xs += part_s[n * 17 + q];
            float xc = xc_s[n * 34 + l];
            float dd = scl_s[l] * (xs - 2.f * xc + csq_s[l]);
            float m = dd;
#pragma unroll
            for (int o = 16; o; o >>= 1) m = fmaxf(m, __shfl_xor_sync(~0u, m, o));
            float e = __expf(dd - m);
            float ss = e;
#pragma unroll
            for (int o = 16; o; o >>= 1) ss += __shfl_xor_sync(~0u, ss, o);
            float a = rtf32(__fdividef(e, ss));   // store A as exact tf32
            wsum_acc += a;
            g_A[((size_t)b * KD + l) * NPIX + n0 + n] = a;   // transposed [k][n]
        }
    }

    wsum_s[w][l] = wsum_acc;
    __syncthreads();
    if (t < KD) {
        float s = 0.f;
#pragma unroll
        for (int ww = 0; ww < 8; ww++) s += wsum_s[ww][t];
        g_wsum[(b * CH1 + ch) * KD + t] = s;
    }
}

// ========== K2: out = A x^T, direct-gmem fragments, no mainloop smem ==========
__global__ __launch_bounds__(256) void enc_k2(const float* __restrict__ x,
                                              const float* __restrict__ cw,
                                              float* __restrict__ out) {
    const int b = blockIdx.x >> 2, cb = blockIdx.x & 3;   // cb: 128-c block
    const int t = threadIdx.x, w = t >> 5, l = t & 31;
    const int mt = w & 1, cq = w >> 1;   // warp = (k-half 16, c-quarter 32)

    __shared__ float wsum_s[KD];
    if (t < KD) {
        float s = 0.f;
#pragma unroll
        for (int ch = 0; ch < CH1; ch++) s += g_wsum[(b * CH1 + ch) * KD + t];
        wsum_s[t] = s;
    }
    __syncthreads();

    float acc[4][4];
#pragma unroll
    for (int i = 0; i < 4; i++)
#pragma unroll
        for (int j = 0; j < 4; j++) acc[i][j] = 0.f;

    // A-fragment row pointers (A already tf32-valued): [b][k][n]
    const float* Ar0 = g_A + ((size_t)b * KD + mt * 16 + (l >> 2)) * NPIX + (l & 3);
    const float* Ar1 = Ar0 + 8 * NPIX;
    // x rows for this warp's 32 c
    const float* xb = x + ((size_t)b * CDIM + cb * 128 + cq * 32 + (l >> 2)) * NPIX + (l & 3);

    for (int n = 0; n < NPIX; n += 8) {
        uint32_t a0 = BITS(__ldg(Ar0 + n));
        uint32_t a1 = BITS(__ldg(Ar1 + n));
        uint32_t a2 = BITS(__ldg(Ar0 + n + 4));
        uint32_t a3 = BITS(__ldg(Ar1 + n + 4));
#pragma unroll
        for (int nt = 0; nt < 4; nt++) {
            const float* xr = xb + (size_t)(nt * 8) * NPIX + n;
            uint32_t b0 = BITS(rtf32(__ldg(xr)));
            uint32_t b1 = BITS(rtf32(__ldg(xr + 4)));
            mma8(acc[nt], a0, a1, a2, a3, b0, b1);
        }
    }

    // fused epilogue: out = acc - wsum*cw
    const int k0 = mt * 16 + (l >> 2);
#pragma unroll
    for (int nt = 0; nt < 4; nt++) {
        int c = cb * 128 + cq * 32 + nt * 8 + 2 * (l & 3);
#pragma unroll
        for (int half = 0; half < 2; half++) {
            int k = k0 + 8 * half;
            float2 cv = __ldg((const float2*)&cw[k * CDIM + c]);
            float ws = wsum_s[k];
            float2 o;
            o.x = acc[nt][2 * half]     - ws * cv.x;
            o.y = acc[nt][2 * half + 1] - ws * cv.y;
            *(float2*)&out[((size_t)b * KD + k) * CDIM + c] = o;
        }
    }
}

extern "C" void kernel_launch(void* const* d_in, const int* in_sizes, int n_in,
                              void* d_out, int out_size) {
    const float* x     = (const float*)d_in[0];
    const float* cw    = (const float*)d_in[1];
    const float* scale = (const float*)d_in[2];
    enc_k1<<<BDIM * CH1, 256>>>(x, cw, scale);
    enc_k2<<<BDIM * 4, 256>>>(x, cw, (float*)d_out);
}

// round 7
// speedup vs baseline: 1.4278x; 1.4278x over previous
#include <cuda_runtime.h>
#include <cstdint>

// Encoding: B=64, C=512, N=784, K=32. x:(B,C,N) f32; out:(B,K,C) f32.
// K1: logits mma tf32 + softmax -> A ([b][n][k], tf32) + wsum partials. Prefetched staging.
// K2: out = A^T x via smem-staged tf32 mma (TS=32, no hi/lo), fused epilogue.

#define CDIM 512
#define KD 32
#define NPIX 784
#define BDIM 64
#define CH1 9
#define TS 16
#define TILES1 49

__device__ float g_A[(size_t)BDIM * NPIX * KD];     // 6.4 MB, [b][n][k]
__device__ float g_wsum[BDIM * CH1 * KD];

__device__ __forceinline__ float rtf32(float v) {
    asm("cvt.rna.tf32.f32 %0, %1;" : "=f"(v) : "f"(v));
    return v;
}
__device__ __forceinline__ void mma8(float* d, uint32_t a0, uint32_t a1,
                                     uint32_t a2, uint32_t a3,
                                     uint32_t b0, uint32_t b1) {
    asm volatile(
        "mma.sync.aligned.m16n8k8.row.col.f32.tf32.tf32.f32 "
        "{%0,%1,%2,%3}, {%4,%5,%6,%7}, {%8,%9}, {%0,%1,%2,%3};"
        : "+f"(d[0]), "+f"(d[1]), "+f"(d[2]), "+f"(d[3])
        : "r"(a0), "r"(a1), "r"(a2), "r"(a3), "r"(b0), "r"(b1));
}
#define BITS(f) __float_as_uint(f)

// =========================== K1: logits + softmax ===========================
__global__ __launch_bounds__(256) void enc_k1(const float* __restrict__ x,
                                              const float* __restrict__ cw,
                                              const float* __restrict__ scale) {
    const int b = blockIdx.x / CH1, ch = blockIdx.x % CH1;
    const int tile0 = ch * TILES1 / CH1, tile1 = (ch + 1) * TILES1 / CH1;
    const int t = threadIdx.x, w = t >> 5, l = t & 31;
    const int kt = w & 3, h = w >> 2;         // warp = (k-tile, c-half)

    __shared__ float x_s[TS * 516];
    __shared__ float xc_s[TS * 34];
    __shared__ float red_s[4 * 32 * 4];
    __shared__ float part_s[TS * 17];
    __shared__ float csq_s[KD], scl_s[KD];
    __shared__ float wsum_s[8][KD];

    if (t < KD) scl_s[t] = __ldg(&scale[t]);
#pragma unroll
    for (int kk = 0; kk < 4; kk++) {
        int k = 4 * w + kk;
        float s = 0.f;
#pragma unroll
        for (int q = 0; q < 4; q++) {
            float4 v = __ldg((const float4*)&cw[k * CDIM + l * 16 + 4 * q]);
            float e0 = rtf32(v.x), e1 = rtf32(v.y), e2 = rtf32(v.z), e3 = rtf32(v.w);
            s += e0 * e0 + e1 * e1 + e2 * e2 + e3 * e3;
        }
#pragma unroll
        for (int o = 16; o; o >>= 1) s += __shfl_xor_sync(~0u, s, o);
        if (l == 0) csq_s[k] = s;
    }

    // persistent codeword B-fragments (tf32): warp covers k=8kt..+7, c-half h
    uint32_t cwf0[32], cwf1[32];
    const int crow = kt * 8 + (l >> 2), cp = l & 3;
#pragma unroll
    for (int s = 0; s < 32; s++) {
        int c = h * 256 + 8 * s + cp;
        cwf0[s] = BITS(rtf32(__ldg(&cw[crow * CDIM + c])));
        cwf1[s] = BITS(rtf32(__ldg(&cw[crow * CDIM + c + 4])));
    }

    float wsum_acc = 0.f;
    const float* xb = x + (size_t)b * CDIM * NPIX;
    const int nl = t & 15, cb16 = t >> 4;

    float buf[32];
#define LDREG(n0) _Pragma("unroll") \
    for (int i = 0; i < 32; i++) buf[i] = __ldg(&xb[(cb16 + 16 * i) * NPIX + (n0) + nl]);

    LDREG(tile0 * TS);
    for (int tile = tile0; tile < tile1; tile++) {
        const int n0 = tile * TS;
        __syncthreads();
        // commit prefetched tile (tf32) + xsq partial
        float xsqp = 0.f;
#pragma unroll
        for (int i = 0; i < 32; i++) {
            float v = rtf32(buf[i]);
            x_s[nl * 516 + cb16 + 16 * i] = v;
            xsqp = fmaf(v, v, xsqp);
        }
        part_s[nl * 17 + cb16] = xsqp;
        __syncthreads();
        if (tile + 1 < tile1) { LDREG(n0 + TS); }   // overlap next-tile DRAM latency

        // phase 1: xc = x . cw^T, 32 k-steps, 2 accumulation chains
        float dA[4] = {0.f, 0.f, 0.f, 0.f}, dB[4] = {0.f, 0.f, 0.f, 0.f};
        const int r0 = (l >> 2) * 516, r1 = ((l >> 2) + 8) * 516;
#pragma unroll
        for (int s = 0; s < 32; s++) {
            int c = h * 256 + 8 * s + cp;
            uint32_t a0 = BITS(x_s[r0 + c]);
            uint32_t a1 = BITS(x_s[r1 + c]);
            uint32_t a2 = BITS(x_s[r0 + c + 4]);
            uint32_t a3 = BITS(x_s[r1 + c + 4]);
            mma8((s & 1) ? dB : dA, a0, a1, a2, a3, cwf0[s], cwf1[s]);
        }
        float d4[4];
#pragma unroll
        for (int i = 0; i < 4; i++) d4[i] = dA[i] + dB[i];
        if (h == 1)
            *(float4*)&red_s[(kt * 32 + l) * 4] = make_float4(d4[0], d4[1], d4[2], d4[3]);
        __syncthreads();
        if (h == 0) {
            float4 rr = *(const float4*)&red_s[(kt * 32 + l) * 4];
            d4[0] += rr.x; d4[1] += rr.y; d4[2] += rr.z; d4[3] += rr.w;
            int rrow = l >> 2, cc = kt * 8 + 2 * (l & 3);
            *(float2*)&xc_s[rrow * 34 + cc] = make_float2(d4[0], d4[1]);
            *(float2*)&xc_s[(rrow + 8) * 34 + cc] = make_float2(d4[2], d4[3]);
        }
        __syncthreads();

        // softmax: warp w rows {w, w+8}, lane = k
#pragma unroll
        for (int r = 0; r < 2; r++) {
            int n = w + 8 * r;
            float xs = 0.f;
#pragma unroll
            for (int q = 0; q < 16; q++) xs += part_s[n * 17 + q];
            float xc = xc_s[n * 34 + l];
            float dd = scl_s[l] * (xs - 2.f * xc + csq_s[l]);
            float m = dd;
#pragma unroll
            for (int o = 16; o; o >>= 1) m = fmaxf(m, __shfl_xor_sync(~0u, m, o));
            float e = __expf(dd - m);
            float ss = e;
#pragma unroll
            for (int o = 16; o; o >>= 1) ss += __shfl_xor_sync(~0u, ss, o);
            float a = rtf32(__fdividef(e, ss));
            wsum_acc += a;
            g_A[((size_t)b * NPIX + n0 + n) * KD + l] = a;   // coalesced
        }
    }

    wsum_s[w][l] = wsum_acc;
    __syncthreads();
    if (t < KD) {
        float s = 0.f;
#pragma unroll
        for (int ww = 0; ww < 8; ww++) s += wsum_s[ww][t];
        g_wsum[(b * CH1 + ch) * KD + t] = s;
    }
}

// ============ K2: out = A^T x, TS=32, tf32 only, fused epilogue ============
__global__ __launch_bounds__(256) void enc_k2(const float* __restrict__ x,
                                              const float* __restrict__ cw,
                                              float* __restrict__ out) {
    const int b = blockIdx.x >> 3, cb = blockIdx.x & 7;   // cb: 64-c block
    const int t = threadIdx.x, w = t >> 5, l = t & 31;
    const int mt = w & 1, cq = w >> 1;   // warp = (k-half 16, c-quarter 16)

    __shared__ float A_s[32 * 40];       // [32n][32k], stride 40
    __shared__ float x_s[64 * 36];       // [64c][32n], stride 36
    __shared__ float wsum_s[KD];

    if (t < KD) {
        float s = 0.f;
#pragma unroll
        for (int ch = 0; ch < CH1; ch++) s += g_wsum[(b * CH1 + ch) * KD + t];
        wsum_s[t] = s;
    }

    float acc[2][4];
#pragma unroll
    for (int i = 0; i < 2; i++)
#pragma unroll
        for (int j = 0; j < 4; j++) acc[i][j] = 0.f;

    const float* xb = x + ((size_t)b * CDIM + cb * 64) * NPIX;
    const float* Ab = g_A + (size_t)b * NPIX * KD;
    const int ar = t >> 3, ak4 = t & 7;   // A staging: row, k-float4
    const int xc_ = t >> 2, xj = t & 3;   // x staging: c row, n-float4

    for (int tl = 0; tl < 25; tl++) {
        const int n0 = tl * 32;
        __syncthreads();
        {   // A tile [32n x 32k], coalesced float4
            float4 av = (n0 + ar < NPIX)
                ? __ldg((const float4*)&Ab[(size_t)(n0 + ar) * KD + 4 * ak4])
                : make_float4(0.f, 0.f, 0.f, 0.f);
            *(float4*)&A_s[ar * 40 + 4 * ak4] = av;
            // x tile [64c x 32n]
#pragma unroll
            for (int i = 0; i < 2; i++) {
                int j = xj + 4 * i;
                float4 v = (n0 + 4 * j < NPIX)
                    ? __ldg((const float4*)&xb[(size_t)xc_ * NPIX + n0 + 4 * j])
                    : make_float4(0.f, 0.f, 0.f, 0.f);
                float* d = &x_s[xc_ * 36 + 4 * j];
                d[0] = rtf32(v.x); d[1] = rtf32(v.y);
                d[2] = rtf32(v.z); d[3] = rtf32(v.w);
            }
        }
        __syncthreads();
#pragma unroll
        for (int ks = 0; ks < 4; ks++) {
            int pn = 8 * ks + (l & 3);
            uint32_t a0 = BITS(A_s[pn * 40 + mt * 16 + (l >> 2)]);
            uint32_t a1 = BITS(A_s[pn * 40 + mt * 16 + (l >> 2) + 8]);
            uint32_t a2 = BITS(A_s[(pn + 4) * 40 + mt * 16 + (l >> 2)]);
            uint32_t a3 = BITS(A_s[(pn + 4) * 40 + mt * 16 + (l >> 2) + 8]);
#pragma unroll
            for (int nt = 0; nt < 2; nt++) {
                int crow = cq * 16 + nt * 8 + (l >> 2);
                uint32_t b0 = BITS(x_s[crow * 36 + pn]);
                uint32_t b1 = BITS(x_s[crow * 36 + pn + 4]);
                mma8(acc[nt], a0, a1, a2, a3, b0, b1);
            }
        }
    }

    // fused epilogue: out = acc - wsum*cw
    const int k0 = mt * 16 + (l >> 2);
#pragma unroll
    for (int nt = 0; nt < 2; nt++) {
        int c = cb * 64 + cq * 16 + nt * 8 + 2 * (l & 3);
#pragma unroll
        for (int half = 0; half < 2; half++) {
            int k = k0 + 8 * half;
            float2 cv = __ldg((const float2*)&cw[k * CDIM + c]);
            float ws = wsum_s[k];
            float2 o;
            o.x = acc[nt][2 * half]     - ws * cv.x;
            o.y = acc[nt][2 * half + 1] - ws * cv.y;
            *(float2*)&out[((size_t)b * KD + k) * CDIM + c] = o;
        }
    }
}

extern "C" void kernel_launch(void* const* d_in, const int* in_sizes, int n_in,
                              void* d_out, int out_size) {
    const float* x     = (const float*)d_in[0];
    const float* cw    = (const float*)d_in[1];
    const float* scale = (const float*)d_in[2];
    enc_k1<<<BDIM * CH1, 256>>>(x, cw, scale);
    enc_k2<<<BDIM * 8, 256>>>(x, cw, (float*)d_out);
}

// round 8
// speedup vs baseline: 1.5328x; 1.0735x over previous
#include <cuda_runtime.h>
#include <cstdint>

// Encoding: B=64, C=512, N=784, K=32. x:(B,C,N) f32; out:(B,K,C) f32.
// K1: logits mma tf32 + softmax -> A ([b][n][k], tf32) + wsum partials. Prefetched staging.
// K2: out = A^T x, tf32 mma, double-buffered smem pipeline (1 sync/tile), fused epilogue.

#define CDIM 512
#define KD 32
#define NPIX 784
#define BDIM 64
#define CH1 9
#define TS 16
#define TILES1 49

__device__ float g_A[(size_t)BDIM * NPIX * KD];     // 6.4 MB, [b][n][k]
__device__ float g_wsum[BDIM * CH1 * KD];

__device__ __forceinline__ float rtf32(float v) {
    asm("cvt.rna.tf32.f32 %0, %1;" : "=f"(v) : "f"(v));
    return v;
}
__device__ __forceinline__ void mma8(float* d, uint32_t a0, uint32_t a1,
                                     uint32_t a2, uint32_t a3,
                                     uint32_t b0, uint32_t b1) {
    asm volatile(
        "mma.sync.aligned.m16n8k8.row.col.f32.tf32.tf32.f32 "
        "{%0,%1,%2,%3}, {%4,%5,%6,%7}, {%8,%9}, {%0,%1,%2,%3};"
        : "+f"(d[0]), "+f"(d[1]), "+f"(d[2]), "+f"(d[3])
        : "r"(a0), "r"(a1), "r"(a2), "r"(a3), "r"(b0), "r"(b1));
}
#define BITS(f) __float_as_uint(f)

// =========================== K1: logits + softmax ===========================
__global__ __launch_bounds__(256) void enc_k1(const float* __restrict__ x,
                                              const float* __restrict__ cw,
                                              const float* __restrict__ scale) {
    const int b = blockIdx.x / CH1, ch = blockIdx.x % CH1;
    const int tile0 = ch * TILES1 / CH1, tile1 = (ch + 1) * TILES1 / CH1;
    const int t = threadIdx.x, w = t >> 5, l = t & 31;
    const int kt = w & 3, h = w >> 2;         // warp = (k-tile, c-half)

    __shared__ float x_s[TS * 516];
    __shared__ float xc_s[TS * 34];
    __shared__ float red_s[4 * 32 * 4];
    __shared__ float part_s[TS * 17];
    __shared__ float csq_s[KD], scl_s[KD];
    __shared__ float wsum_s[8][KD];

    if (t < KD) scl_s[t] = __ldg(&scale[t]);
#pragma unroll
    for (int kk = 0; kk < 4; kk++) {
        int k = 4 * w + kk;
        float s = 0.f;
#pragma unroll
        for (int q = 0; q < 4; q++) {
            float4 v = __ldg((const float4*)&cw[k * CDIM + l * 16 + 4 * q]);
            float e0 = rtf32(v.x), e1 = rtf32(v.y), e2 = rtf32(v.z), e3 = rtf32(v.w);
            s += e0 * e0 + e1 * e1 + e2 * e2 + e3 * e3;
        }
#pragma unroll
        for (int o = 16; o; o >>= 1) s += __shfl_xor_sync(~0u, s, o);
        if (l == 0) csq_s[k] = s;
    }

    // persistent codeword B-fragments (tf32): warp covers k=8kt..+7, c-half h
    uint32_t cwf0[32], cwf1[32];
    const int crow = kt * 8 + (l >> 2), cp = l & 3;
#pragma unroll
    for (int s = 0; s < 32; s++) {
        int c = h * 256 + 8 * s + cp;
        cwf0[s] = BITS(rtf32(__ldg(&cw[crow * CDIM + c])));
        cwf1[s] = BITS(rtf32(__ldg(&cw[crow * CDIM + c + 4])));
    }

    float wsum_acc = 0.f;
    const float* xb = x + (size_t)b * CDIM * NPIX;
    const int nl = t & 15, cb16 = t >> 4;

    float buf[32];
#define LDREG(n0) _Pragma("unroll") \
    for (int i = 0; i < 32; i++) buf[i] = __ldg(&xb[(cb16 + 16 * i) * NPIX + (n0) + nl]);

    LDREG(tile0 * TS);
    for (int tile = tile0; tile < tile1; tile++) {
        const int n0 = tile * TS;
        __syncthreads();
        // commit prefetched tile (tf32) + xsq partial
        float xsqp = 0.f;
#pragma unroll
        for (int i = 0; i < 32; i++) {
            float v = rtf32(buf[i]);
            x_s[nl * 516 + cb16 + 16 * i] = v;
            xsqp = fmaf(v, v, xsqp);
        }
        part_s[nl * 17 + cb16] = xsqp;
        __syncthreads();
        if (tile + 1 < tile1) { LDREG(n0 + TS); }   // overlap next-tile DRAM latency

        // phase 1: xc = x . cw^T, 32 k-steps, 2 accumulation chains
        float dA[4] = {0.f, 0.f, 0.f, 0.f}, dB[4] = {0.f, 0.f, 0.f, 0.f};
        const int r0 = (l >> 2) * 516, r1 = ((l >> 2) + 8) * 516;
#pragma unroll
        for (int s = 0; s < 32; s++) {
            int c = h * 256 + 8 * s + cp;
            uint32_t a0 = BITS(x_s[r0 + c]);
            uint32_t a1 = BITS(x_s[r1 + c]);
            uint32_t a2 = BITS(x_s[r0 + c + 4]);
            uint32_t a3 = BITS(x_s[r1 + c + 4]);
            mma8((s & 1) ? dB : dA, a0, a1, a2, a3, cwf0[s], cwf1[s]);
        }
        float d4[4];
#pragma unroll
        for (int i = 0; i < 4; i++) d4[i] = dA[i] + dB[i];
        if (h == 1)
            *(float4*)&red_s[(kt * 32 + l) * 4] = make_float4(d4[0], d4[1], d4[2], d4[3]);
        __syncthreads();
        if (h == 0) {
            float4 rr = *(const float4*)&red_s[(kt * 32 + l) * 4];
            d4[0] += rr.x; d4[1] += rr.y; d4[2] += rr.z; d4[3] += rr.w;
            int rrow = l >> 2, cc = kt * 8 + 2 * (l & 3);
            *(float2*)&xc_s[rrow * 34 + cc] = make_float2(d4[0], d4[1]);
            *(float2*)&xc_s[(rrow + 8) * 34 + cc] = make_float2(d4[2], d4[3]);
        }
        __syncthreads();

        // softmax: warp w rows {w, w+8}, lane = k
#pragma unroll
        for (int r = 0; r < 2; r++) {
            int n = w + 8 * r;
            float xs = 0.f;
#pragma unroll
            for (int q = 0; q < 16; q++) xs += part_s[n * 17 + q];
            float xc = xc_s[n * 34 + l];
            float dd = scl_s[l] * (xs - 2.f * xc + csq_s[l]);
            float m = dd;
#pragma unroll
            for (int o = 16; o; o >>= 1) m = fmaxf(m, __shfl_xor_sync(~0u, m, o));
            float e = __expf(dd - m);
            float ss = e;
#pragma unroll
            for (int o = 16; o; o >>= 1) ss += __shfl_xor_sync(~0u, ss, o);
            float a = rtf32(__fdividef(e, ss));
            wsum_acc += a;
            g_A[((size_t)b * NPIX + n0 + n) * KD + l] = a;   // coalesced
        }
    }

    wsum_s[w][l] = wsum_acc;
    __syncthreads();
    if (t < KD) {
        float s = 0.f;
#pragma unroll
        for (int ww = 0; ww < 8; ww++) s += wsum_s[ww][t];
        g_wsum[(b * CH1 + ch) * KD + t] = s;
    }
}

// ==== K2: out = A^T x, double-buffered pipeline (1 sync/tile), fused epilogue ====
__global__ __launch_bounds__(256) void enc_k2(const float* __restrict__ x,
                                              const float* __restrict__ cw,
                                              float* __restrict__ out) {
    const int b = blockIdx.x >> 3, cb = blockIdx.x & 7;   // cb: 64-c block
    const int t = threadIdx.x, w = t >> 5, l = t & 31;
    const int mt = w & 1, cq = w >> 1;   // warp = (k-half 16, c-quarter 16)

    __shared__ float A_s[2][32 * 40];    // [32n][32k], stride 40
    __shared__ float x_s[2][64 * 36];    // [64c][32n], stride 36
    __shared__ float wsum_s[KD];

    if (t < KD) {
        float s = 0.f;
#pragma unroll
        for (int ch = 0; ch < CH1; ch++) s += g_wsum[(b * CH1 + ch) * KD + t];
        wsum_s[t] = s;
    }

    float acc[2][4];
#pragma unroll
    for (int i = 0; i < 2; i++)
#pragma unroll
        for (int j = 0; j < 4; j++) acc[i][j] = 0.f;

    const float* xb = x + ((size_t)b * CDIM + cb * 64) * NPIX;
    const float* Ab = g_A + (size_t)b * NPIX * KD;
    const int ar = t >> 3, ak4 = t & 7;   // A staging: row, k-float4
    const int xc_ = t >> 2, xj = t & 3;   // x staging: c row, n-float4

#define K2_LDG(n0, av, v0, v1) do { \
        av = ((n0) + ar < NPIX) \
            ? __ldg((const float4*)&Ab[(size_t)((n0) + ar) * KD + 4 * ak4]) \
            : make_float4(0.f, 0.f, 0.f, 0.f); \
        v0 = ((n0) + 4 * xj < NPIX) \
            ? __ldg((const float4*)&xb[(size_t)xc_ * NPIX + (n0) + 4 * xj]) \
            : make_float4(0.f, 0.f, 0.f, 0.f); \
        v1 = ((n0) + 4 * (xj + 4) < NPIX) \
            ? __ldg((const float4*)&xb[(size_t)xc_ * NPIX + (n0) + 4 * (xj + 4)]) \
            : make_float4(0.f, 0.f, 0.f, 0.f); \
    } while (0)

#define K2_STS(bi, av, v0, v1) do { \
        *(float4*)&A_s[bi][ar * 40 + 4 * ak4] = av; \
        float* d0 = &x_s[bi][xc_ * 36 + 4 * xj]; \
        d0[0] = rtf32(v0.x); d0[1] = rtf32(v0.y); d0[2] = rtf32(v0.z); d0[3] = rtf32(v0.w); \
        float* d1 = &x_s[bi][xc_ * 36 + 4 * (xj + 4)]; \
        d1[0] = rtf32(v1.x); d1[1] = rtf32(v1.y); d1[2] = rtf32(v1.z); d1[3] = rtf32(v1.w); \
    } while (0)

    {   // prologue: stage tile 0 into buffer 0
        float4 av, v0, v1;
        K2_LDG(0, av, v0, v1);
        K2_STS(0, av, v0, v1);
    }
    __syncthreads();

    for (int tl = 0; tl < 25; tl++) {
        const int cur = tl & 1;
        float4 av, v0, v1;
        if (tl < 24) { K2_LDG((tl + 1) * 32, av, v0, v1); }   // overlap with mma

#pragma unroll
        for (int ks = 0; ks < 4; ks++) {
            int pn = 8 * ks + (l & 3);
            uint32_t a0 = BITS(A_s[cur][pn * 40 + mt * 16 + (l >> 2)]);
            uint32_t a1 = BITS(A_s[cur][pn * 40 + mt * 16 + (l >> 2) + 8]);
            uint32_t a2 = BITS(A_s[cur][(pn + 4) * 40 + mt * 16 + (l >> 2)]);
            uint32_t a3 = BITS(A_s[cur][(pn + 4) * 40 + mt * 16 + (l >> 2) + 8]);
#pragma unroll
            for (int nt = 0; nt < 2; nt++) {
                int crow = cq * 16 + nt * 8 + (l >> 2);
                uint32_t b0 = BITS(x_s[cur][crow * 36 + pn]);
                uint32_t b1 = BITS(x_s[cur][crow * 36 + pn + 4]);
                mma8(acc[nt], a0, a1, a2, a3, b0, b1);
            }
        }
        if (tl < 24) { K2_STS(1 - cur, av, v0, v1); }   // write other buffer
        __syncthreads();
    }

    // fused epilogue: out = acc - wsum*cw
    const int k0 = mt * 16 + (l >> 2);
#pragma unroll
    for (int nt = 0; nt < 2; nt++) {
        int c = cb * 64 + cq * 16 + nt * 8 + 2 * (l & 3);
#pragma unroll
        for (int half = 0; half < 2; half++) {
            int k = k0 + 8 * half;
            float2 cv = __ldg((const float2*)&cw[k * CDIM + c]);
            float ws = wsum_s[k];
            float2 o;
            o.x = acc[nt][2 * half]     - ws * cv.x;
            o.y = acc[nt][2 * half + 1] - ws * cv.y;
            *(float2*)&out[((size_t)b * KD + k) * CDIM + c] = o;
        }
    }
}

extern "C" void kernel_launch(void* const* d_in, const int* in_sizes, int n_in,
                              void* d_out, int out_size) {
    const float* x     = (const float*)d_in[0];
    const float* cw    = (const float*)d_in[1];
    const float* scale = (const float*)d_in[2];
    enc_k1<<<BDIM * CH1, 256>>>(x, cw, scale);
    enc_k2<<<BDIM * 8, 256>>>(x, cw, (float*)d_out);
}